// round 12
// baseline (speedup 1.0000x reference)
#include <cuda_runtime.h>
#include <cuda_bf16.h>
#include <cstdint>

// SSL2d: per-channel sub-pixel bilinear shift with zero padding.
// x: [B=32, C=384, H=56, W=56] fp32, a,b: [C] fp32.
//
// R12: persistent kernel, done right this time.
//  - grid = 1332 CTAs (exact 9/SM residency, single wave)
//  - each CTA owns a CONTIGUOUS balanced chunk of planes (long DRAM streams)
//  - next plane's a/b prefetched one iteration ahead (kills the serial
//    setup chain that sank the R7 grid-stride attempt)
//  - inner mapping = proven R4/R8: 224 thr, 4 rows/thread, 5x LDG.128 (MLP=5),
//    warp-shuffle boundary column, factored blend, __stcs stores.

#define SSL_H 56
#define SSL_W 56
#define SSL_C 384
#define SSL_B 32
#define NPLANES (SSL_B * SSL_C)             // 12288
#define NTHREADS 224                        // 14 rowgroups * 16 lanes
#define GRID_CTAS 1332                      // 148 SMs * 9 resident CTAs

__global__ __launch_bounds__(NTHREADS, 7)
void ssl2d_kernel(const float* __restrict__ x,
                  const float* __restrict__ a,
                  const float* __restrict__ b,
                  float* __restrict__ out) {
    const int tid = threadIdx.x;
    const int j = tid & 15;                 // lane within rowgroup (14,15 idle)
    const int rg = tid >> 4;                // rowgroup 0..13
    const int hbase = rg << 2;              // first output row of this thread
    const int w = j << 2;
    const bool active = (j < 14);

    // contiguous balanced chunk of planes for this CTA
    const int pstart = (int)(((long long)blockIdx.x * NPLANES) / GRID_CTAS);
    const int pend   = (int)(((long long)(blockIdx.x + 1) * NPLANES) / GRID_CTAS);
    if (pstart >= pend) return;

    // prime the a/b pipeline
    int c0 = pstart - (pstart / SSL_C) * SSL_C;
    float av = __ldg(a + c0);
    float bv = __ldg(b + c0);

    for (int plane = pstart; plane < pend; ++plane) {
        // prefetch next plane's shift params (independent of this iteration)
        float av_n = 0.f, bv_n = 0.f;
        if (plane + 1 < pend) {
            int cn = (plane + 1) - ((plane + 1) / SSL_C) * SSL_C;
            av_n = __ldg(a + cn);
            bv_n = __ldg(b + cn);
        }

        const float iaf = floorf(av);
        const float ibf = floorf(bv);
        const float fa = av - iaf;
        const float fb = bv - ibf;
        const int ia = (int)iaf;
        const int ib = (int)ibf;

        const float* __restrict__ xp = x + (size_t)plane * (SSL_H * SSL_W);
        float* __restrict__ op       = out + (size_t)plane * (SSL_H * SSL_W);

        if (ia >= -1 && ia <= 0 && ib >= -1 && ib <= 0) {
            // ---- fast path: 5 source-row LDG.128 issued up-front ----
            float4 q[5];
            #pragma unroll
            for (int k = 0; k < 5; k++) {
                const int s = hbase + ia + k;
                q[k] = make_float4(0.f, 0.f, 0.f, 0.f);
                if (active & (s >= 0) & (s < SSL_H))
                    q[k] = *reinterpret_cast<const float4*>(xp + s * SSL_W + w);
            }

            const float fb1 = 1.0f - fb;
            float4 Hk[5];
            if (ib == 0) {
                #pragma unroll
                for (int k = 0; k < 5; k++) {
                    float e = __shfl_down_sync(0xffffffffu, q[k].x, 1); // col w+4
                    if (j >= 13) e = 0.f;                               // w+4 >= 56
                    Hk[k].x = fb1 * q[k].x + fb * q[k].y;
                    Hk[k].y = fb1 * q[k].y + fb * q[k].z;
                    Hk[k].z = fb1 * q[k].z + fb * q[k].w;
                    Hk[k].w = fb1 * q[k].w + fb * e;
                }
            } else {
                #pragma unroll
                for (int k = 0; k < 5; k++) {
                    float e = __shfl_up_sync(0xffffffffu, q[k].w, 1);   // col w-1
                    if (j == 0) e = 0.f;                                // w-1 < 0
                    Hk[k].x = fb1 * e       + fb * q[k].x;
                    Hk[k].y = fb1 * q[k].x  + fb * q[k].y;
                    Hk[k].z = fb1 * q[k].y  + fb * q[k].z;
                    Hk[k].w = fb1 * q[k].z  + fb * q[k].w;
                }
            }

            if (active) {
                const float fa1 = 1.0f - fa;
                #pragma unroll
                for (int r = 0; r < 4; r++) {
                    float4 o;
                    o.x = fa1 * Hk[r].x + fa * Hk[r + 1].x;
                    o.y = fa1 * Hk[r].y + fa * Hk[r + 1].y;
                    o.z = fa1 * Hk[r].z + fa * Hk[r + 1].z;
                    o.w = fa1 * Hk[r].w + fa * Hk[r + 1].w;
                    __stcs(reinterpret_cast<float4*>(op + (hbase + r) * SSL_W + w), o);
                }
            }
        } else if (active) {
            // ---- generic fallback (shifts outside [-1,0]) ----
            const float w00 = (1.0f - fa) * (1.0f - fb);
            const float w01 = (1.0f - fa) * fb;
            const float w10 = fa * (1.0f - fb);
            const float w11 = fa * fb;

            #pragma unroll
            for (int r = 0; r < 4; r++) {
                const int h = hbase + r;
                const int h0 = h + ia;
                const int h1 = h0 + 1;
                const bool vh0 = (h0 >= 0) & (h0 < SSL_H);
                const bool vh1 = (h1 >= 0) & (h1 < SSL_H);
                const int wbase = w + ib;
                const float* row0 = xp + h0 * SSL_W;
                const float* row1 = xp + h1 * SSL_W;

                float r0[5], r1[5];
                #pragma unroll
                for (int i = 0; i < 5; i++) {
                    const int ws = wbase + i;
                    const bool vw = (ws >= 0) & (ws < SSL_W);
                    r0[i] = (vh0 & vw) ? __ldg(row0 + ws) : 0.0f;
                    r1[i] = (vh1 & vw) ? __ldg(row1 + ws) : 0.0f;
                }

                float4 o;
                o.x = w00 * r0[0] + w01 * r0[1] + w10 * r1[0] + w11 * r1[1];
                o.y = w00 * r0[1] + w01 * r0[2] + w10 * r1[1] + w11 * r1[2];
                o.z = w00 * r0[2] + w01 * r0[3] + w10 * r1[2] + w11 * r1[3];
                o.w = w00 * r0[3] + w01 * r0[4] + w10 * r1[3] + w11 * r1[4];
                __stcs(reinterpret_cast<float4*>(op + h * SSL_W + w), o);
            }
        }

        av = av_n;
        bv = bv_n;
    }
}

extern "C" void kernel_launch(void* const* d_in, const int* in_sizes, int n_in,
                              void* d_out, int out_size) {
    const float* x = (const float*)d_in[0];
    const float* a = (const float*)d_in[1];
    const float* b = (const float*)d_in[2];
    float* out = (float*)d_out;

    ssl2d_kernel<<<GRID_CTAS, NTHREADS>>>(x, a, b, out);
}

// round 13
// speedup vs baseline: 1.1651x; 1.1651x over previous
#include <cuda_runtime.h>
#include <cuda_bf16.h>
#include <cstdint>

// SSL2d: per-channel sub-pixel bilinear shift with zero padding.
// x: [B=32, C=384, H=56, W=56] fp32, a,b: [C] fp32.
//
// R13: one CTA per plane (grid 12288, the winning structure), deepened to
// 7 output rows per thread:
//  - block 128 = 8 rowgroups x 16 lanes (14 active), thread owns rows rg*7..rg*7+6
//  - 8 source-row LDG.128 issued up-front (MLP=8)
//  - rolling horizontal blend (H[k] consumed into row k-1's store immediately)
//    keeps live registers ~q[8] + a few
//  - warp shuffle for the single boundary column per source row (seam cases
//    forced-zero, identical logic to R8)
//  - __stcs streaming stores

#define SSL_H 56
#define SSL_W 56
#define SSL_C 384
#define ROWS_PT 7                           // output rows per thread
#define NRG (SSL_H / ROWS_PT)               // 8 rowgroups
#define NTHREADS (NRG * 16)                 // 128

__global__ __launch_bounds__(NTHREADS, 12)
void ssl2d_kernel(const float* __restrict__ x,
                  const float* __restrict__ a,
                  const float* __restrict__ b,
                  float* __restrict__ out) {
    const int plane = blockIdx.x;           // n * C + c
    const int c = plane - (plane / SSL_C) * SSL_C;

    const float av = __ldg(a + c);
    const float bv = __ldg(b + c);
    const float iaf = floorf(av);
    const float ibf = floorf(bv);
    const float fa = av - iaf;
    const float fb = bv - ibf;
    const int ia = (int)iaf;
    const int ib = (int)ibf;

    const float* __restrict__ xp = x + (size_t)plane * (SSL_H * SSL_W);
    float* __restrict__ op       = out + (size_t)plane * (SSL_H * SSL_W);

    const int tid = threadIdx.x;
    const int j = tid & 15;                 // lane within rowgroup (14,15 idle)
    const int rg = tid >> 4;                // rowgroup 0..7
    const int hbase = rg * ROWS_PT;         // first output row of this thread
    const int w = j << 2;
    const bool active = (j < 14);

    if (ia >= -1 && ia <= 0 && ib >= -1 && ib <= 0) {
        // ---- fast path: 8 source-row LDG.128 issued up-front ----
        float4 q[ROWS_PT + 1];
        #pragma unroll
        for (int k = 0; k <= ROWS_PT; k++) {
            const int s = hbase + ia + k;
            q[k] = make_float4(0.f, 0.f, 0.f, 0.f);
            if (active & (s >= 0) & (s < SSL_H))
                q[k] = *reinterpret_cast<const float4*>(xp + s * SSL_W + w);
        }

        const float fb1 = 1.0f - fb;
        const float fa1 = 1.0f - fa;

        // rolling horizontal blend + vertical blend + store
        float4 Hp;                           // H[k-1]
        #pragma unroll
        for (int k = 0; k <= ROWS_PT; k++) {
            float4 Hc;
            if (ib == 0) {
                float e = __shfl_down_sync(0xffffffffu, q[k].x, 1); // col w+4
                if (j >= 13) e = 0.f;                               // w+4 >= 56
                Hc.x = fb1 * q[k].x + fb * q[k].y;
                Hc.y = fb1 * q[k].y + fb * q[k].z;
                Hc.z = fb1 * q[k].z + fb * q[k].w;
                Hc.w = fb1 * q[k].w + fb * e;
            } else {
                float e = __shfl_up_sync(0xffffffffu, q[k].w, 1);   // col w-1
                if (j == 0) e = 0.f;                                // w-1 < 0
                Hc.x = fb1 * e      + fb * q[k].x;
                Hc.y = fb1 * q[k].x + fb * q[k].y;
                Hc.z = fb1 * q[k].y + fb * q[k].z;
                Hc.w = fb1 * q[k].z + fb * q[k].w;
            }

            if (k > 0 && active) {
                float4 o;
                o.x = fa1 * Hp.x + fa * Hc.x;
                o.y = fa1 * Hp.y + fa * Hc.y;
                o.z = fa1 * Hp.z + fa * Hc.z;
                o.w = fa1 * Hp.w + fa * Hc.w;
                __stcs(reinterpret_cast<float4*>(op + (hbase + k - 1) * SSL_W + w), o);
            }
            Hp = Hc;
        }
    } else if (active) {
        // ---- generic fallback (shifts outside [-1,0]): predicated scalar LDG ----
        const float w00 = (1.0f - fa) * (1.0f - fb);
        const float w01 = (1.0f - fa) * fb;
        const float w10 = fa * (1.0f - fb);
        const float w11 = fa * fb;

        #pragma unroll
        for (int r = 0; r < ROWS_PT; r++) {
            const int h = hbase + r;
            const int h0 = h + ia;
            const int h1 = h0 + 1;
            const bool vh0 = (h0 >= 0) & (h0 < SSL_H);
            const bool vh1 = (h1 >= 0) & (h1 < SSL_H);
            const int wbase = w + ib;
            const float* row0 = xp + h0 * SSL_W;
            const float* row1 = xp + h1 * SSL_W;

            float r0[5], r1[5];
            #pragma unroll
            for (int i = 0; i < 5; i++) {
                const int ws = wbase + i;
                const bool vw = (ws >= 0) & (ws < SSL_W);
                r0[i] = (vh0 & vw) ? __ldg(row0 + ws) : 0.0f;
                r1[i] = (vh1 & vw) ? __ldg(row1 + ws) : 0.0f;
            }

            float4 o;
            o.x = w00 * r0[0] + w01 * r0[1] + w10 * r1[0] + w11 * r1[1];
            o.y = w00 * r0[1] + w01 * r0[2] + w10 * r1[1] + w11 * r1[2];
            o.z = w00 * r0[2] + w01 * r0[3] + w10 * r1[2] + w11 * r1[3];
            o.w = w00 * r0[3] + w01 * r0[4] + w10 * r1[3] + w11 * r1[4];
            __stcs(reinterpret_cast<float4*>(op + h * SSL_W + w), o);
        }
    }
}

extern "C" void kernel_launch(void* const* d_in, const int* in_sizes, int n_in,
                              void* d_out, int out_size) {
    const float* x = (const float*)d_in[0];
    const float* a = (const float*)d_in[1];
    const float* b = (const float*)d_in[2];
    float* out = (float*)d_out;

    const int B = 32;
    const int planes = B * SSL_C;           // 12288
    ssl2d_kernel<<<planes, NTHREADS>>>(x, a, b, out);
}